// round 10
// baseline (speedup 1.0000x reference)
#include <cuda_runtime.h>

// AREMA: attack/release envelope follower.
// y_t = alpha*x_t + (1-alpha)*y_{t-1}, alpha = a if (x_t - y_{t-1} > 0) else r.
// Since a > r > 0:  y_t = max( fma(a, x-y, y), fma(r, x-y, y) ).
//
// Chunked along T with warm-up (calibrated: err(W)=0.0964*exp(-0.0527*W);
// W=96 -> 6.1e-4 predicted, 6.12e-4 measured twice). CHUNKS=32.
//
// R10: float4 lanes (LDG.128/STG.128), 4 chains/thread, triple-buffered
// (2 batches = 8KB/warp in flight), 32-thread blocks for load balance
// (1024 blocks ~ 6.92/SM). Width probe R9 (float2) gave +7% BW; extending.

#define BB 8
#define TT 16384
#define FF4 128             // feature columns in float4 units (512 floats)
#define CHUNKS 32
#define LCH (TT / CHUNKS)   // 512 outputs per chunk -> 64 phases of UNR=8
#define WARM 96             // warm-up steps -> 12 phases (4 triples)
#define UNR 8

#define LOAD(buf)                                                   \
    _Pragma("unroll")                                               \
    for (int u = 0; u < UNR; ++u) buf[u] = xp[u * FF4];             \
    xp += UNR * FF4;

#define STEP(v)                                                     \
    {                                                               \
        float d0 = (v).x - y0;                                      \
        float d1 = (v).y - y1;                                      \
        float d2 = (v).z - y2;                                      \
        float d3 = (v).w - y3;                                      \
        y0 = fmaxf(fmaf(A, d0, y0), fmaf(R, d0, y0));               \
        y1 = fmaxf(fmaf(A, d1, y1), fmaf(R, d1, y1));               \
        y2 = fmaxf(fmaf(A, d2, y2), fmaf(R, d2, y2));               \
        y3 = fmaxf(fmaf(A, d3, y3), fmaf(R, d3, y3));               \
    }

#define COMP(buf)                                                   \
    _Pragma("unroll")                                               \
    for (int u = 0; u < UNR; ++u) STEP(buf[u])

#define COMPST(buf)                                                 \
    _Pragma("unroll")                                               \
    for (int u = 0; u < UNR; ++u) {                                 \
        STEP(buf[u])                                                \
        float4 o; o.x = y0; o.y = y1; o.z = y2; o.w = y3;           \
        __stcs(yp + u * FF4, o);                                    \
    }                                                               \
    yp += UNR * FF4;

__global__ __launch_bounds__(32)
void arema_kernel(const float4* __restrict__ x, float4* __restrict__ y) {
    const float A = 0.18126924692201818f;   // 1 - exp(-0.001/0.005)
    const float R = 0.019801326693244747f;  // 1 - exp(-0.001/0.05)

    const int f4 = blockIdx.x * 32 + threadIdx.x;   // float4 lane (coalesced)
    const int b  = blockIdx.y;                      // batch
    const int c  = blockIdx.z;                      // chunk along T

    const int t0    = c * LCH;
    const int nwarm = (c == 0) ? 0 : WARM;          // first chunk: exact

    const float4* xp = x + (b * TT + t0 - nwarm) * FF4 + f4;
    float4*       yp = y + (b * TT + t0) * FF4 + f4;

    float4 bufA[UNR], bufB[UNR], bufC[UNR];
    float y0 = 0.0f, y1 = 0.0f, y2 = 0.0f, y3 = 0.0f;

    // ---- prologue: 2 batches in flight ----
    LOAD(bufA)
    LOAD(bufB)

    // ---- warm-up (read-only), triple-buffered: 12 phases = 4 triples ----
    const int warmTriples = nwarm / (3 * UNR);      // 4 or 0
    for (int i = 0; i < warmTriples; ++i) {
        LOAD(bufC)
        COMP(bufA)
        LOAD(bufA)
        COMP(bufB)
        LOAD(bufB)
        COMP(bufC)
    }

    // ---- main: 64 phases = 20 triples + 4-phase tail ----
    for (int i = 0; i < 20; ++i) {
        LOAD(bufC)
        COMPST(bufA)
        LOAD(bufA)
        COMPST(bufB)
        LOAD(bufB)
        COMPST(bufC)
    }
    // tail: 2 more loads, 4 more consumes (A,B in flight here)
    LOAD(bufC)
    COMPST(bufA)
    LOAD(bufA)
    COMPST(bufB)
    COMPST(bufC)
    COMPST(bufA)
}

extern "C" void kernel_launch(void* const* d_in, const int* in_sizes, int n_in,
                              void* d_out, int out_size) {
    const float4* x = (const float4*)d_in[0];
    float4*       y = (float4*)d_out;
    dim3 grid(FF4 / 32, BB, CHUNKS);  // (4, 8, 32) = 1024 blocks x 32 threads
    arema_kernel<<<grid, 32>>>(x, y);
}